// round 1
// baseline (speedup 1.0000x reference)
#include <cuda_runtime.h>
#include <math.h>

#define N_NODES 50000
#define E_EDGES 1600000
#define ETOT    (E_EDGES + N_NODES)
#define NEG_SLOPE 0.2f
#define BN_EPS 1e-5f

// ---------------- scratch (static device globals; no allocation) ------------
__device__ float g_bufA[(size_t)N_NODES * 128];
__device__ float g_bufB[(size_t)N_NODES * 128];
__device__ float g_bufC[(size_t)N_NODES * 128];
__device__ float g_bufD[(size_t)N_NODES * 64];
__device__ float g_bufE[(size_t)N_NODES * 64];
__device__ float g_bufF[(size_t)N_NODES * 64];
__device__ float g_als[N_NODES * 2];
__device__ float g_ald[N_NODES * 2];
__device__ float g_emax[N_NODES * 2];
__device__ float g_esum[N_NODES * 2];
__device__ float g_cnt[N_NODES];

// ---------------- helpers ----------------------------------------------------
__device__ __forceinline__ float lrelu(float x) {
    return x > 0.0f ? x : NEG_SLOPE * x;
}

__device__ __forceinline__ void atomicMaxF(float* addr, float v) {
    if (v >= 0.0f)
        atomicMax((int*)addr, __float_as_int(v));
    else
        atomicMin((unsigned int*)addr, __float_as_uint(v));
}

__global__ void fill_kernel(float* __restrict__ p, float v, int n) {
    int i = blockIdx.x * blockDim.x + threadIdx.x;
    if (i < n) p[i] = v;
}

// ---------------- SGEMM: C[M,NC] = A[M,K] @ B[K,NC] -------------------------
// BM=128 BN=64 BK=16 TM=8 TN=4, 256 threads. K in {64,128,256}, NC in {64,128}.
#define BM 128
#define BN 64
#define BK 16
#define TM 8
#define TN 4

__global__ __launch_bounds__(256) void sgemm_kernel(
    const float* __restrict__ A, const float* __restrict__ B,
    float* __restrict__ C, int M, int K, int NC)
{
    __shared__ float As[BK][BM];
    __shared__ float Bs[BK][BN];

    int tid = threadIdx.x;
    int rowBase = blockIdx.x * BM;
    int colBase = blockIdx.y * BN;
    int tx = tid & 15;   // column group (TN=4)
    int ty = tid >> 4;   // row group (TM=8)

    float acc[TM][TN];
    #pragma unroll
    for (int i = 0; i < TM; i++)
        #pragma unroll
        for (int j = 0; j < TN; j++) acc[i][j] = 0.0f;

    int ar0 = tid >> 2;          // 0..63 (row within half-tile)
    int ac  = (tid & 3) * 4;     // k offset: 0,4,8,12
    int br  = tid >> 4;          // 0..15 (k row)
    int bc  = (tid & 15) * 4;    // 0..60

    for (int k0 = 0; k0 < K; k0 += BK) {
        #pragma unroll
        for (int i = 0; i < 2; i++) {
            int r  = ar0 + i * 64;
            int gr = rowBase + r;
            float4 v = make_float4(0.f, 0.f, 0.f, 0.f);
            if (gr < M) v = *(const float4*)(A + (size_t)gr * K + k0 + ac);
            As[ac + 0][r] = v.x;
            As[ac + 1][r] = v.y;
            As[ac + 2][r] = v.z;
            As[ac + 3][r] = v.w;
        }
        {
            float4 v = *(const float4*)(B + (size_t)(k0 + br) * NC + colBase + bc);
            Bs[br][bc + 0] = v.x;
            Bs[br][bc + 1] = v.y;
            Bs[br][bc + 2] = v.z;
            Bs[br][bc + 3] = v.w;
        }
        __syncthreads();

        #pragma unroll
        for (int kk = 0; kk < BK; kk++) {
            float a[TM], b[TN];
            #pragma unroll
            for (int i = 0; i < TM; i++) a[i] = As[kk][ty * TM + i];
            #pragma unroll
            for (int j = 0; j < TN; j++) b[j] = Bs[kk][tx * TN + j];
            #pragma unroll
            for (int i = 0; i < TM; i++)
                #pragma unroll
                for (int j = 0; j < TN; j++) acc[i][j] = fmaf(a[i], b[j], acc[i][j]);
        }
        __syncthreads();
    }

    #pragma unroll
    for (int i = 0; i < TM; i++) {
        int gr = rowBase + ty * TM + i;
        if (gr < M) {
            float4 v = make_float4(acc[i][0], acc[i][1], acc[i][2], acc[i][3]);
            *(float4*)(C + (size_t)gr * NC + colBase + tx * TN) = v;
        }
    }
}

// ---------------- GAT attention-logit precompute -----------------------------
// One warp per node: al_src[n][h] = sum_c h[n][h*64+c]*a_src[h*64+c]
__global__ void compute_al_kernel(
    const float* __restrict__ h, const float* __restrict__ a_src,
    const float* __restrict__ a_dst, float* __restrict__ als,
    float* __restrict__ ald)
{
    int warp = (blockIdx.x * blockDim.x + threadIdx.x) >> 5;
    int lane = threadIdx.x & 31;
    if (warp >= N_NODES) return;

    float4 hv = *(const float4*)(h + (size_t)warp * 128 + lane * 4);
    float4 as = *(const float4*)(a_src + lane * 4);
    float4 ad = *(const float4*)(a_dst + lane * 4);
    float ss = hv.x * as.x + hv.y * as.y + hv.z * as.z + hv.w * as.w;
    float sd = hv.x * ad.x + hv.y * ad.y + hv.z * ad.z + hv.w * ad.w;
    // lanes 0..15 = head0 (cols 0..63), lanes 16..31 = head1
    #pragma unroll
    for (int o = 8; o; o >>= 1) {
        ss += __shfl_xor_sync(0xffffffffu, ss, o);
        sd += __shfl_xor_sync(0xffffffffu, sd, o);
    }
    if (lane == 0)  { als[warp * 2 + 0] = ss; ald[warp * 2 + 0] = sd; }
    if (lane == 16) { als[warp * 2 + 1] = ss; ald[warp * 2 + 1] = sd; }
}

// ---------------- GAT edge passes --------------------------------------------
__global__ void edge_max_kernel(
    const int* __restrict__ src, const int* __restrict__ dst,
    const float* __restrict__ als, const float* __restrict__ ald,
    float* __restrict__ emax)
{
    int e = blockIdx.x * blockDim.x + threadIdx.x;
    if (e >= ETOT) return;
    int s, d;
    if (e < E_EDGES) { s = src[e]; d = dst[e]; } else { s = d = e - E_EDGES; }
    float2 a = *(const float2*)(als + s * 2);
    float2 b = *(const float2*)(ald + d * 2);
    atomicMaxF(&emax[d * 2 + 0], lrelu(a.x + b.x));
    atomicMaxF(&emax[d * 2 + 1], lrelu(a.y + b.y));
}

__global__ void edge_sum_kernel(
    const int* __restrict__ src, const int* __restrict__ dst,
    const float* __restrict__ als, const float* __restrict__ ald,
    const float* __restrict__ emax, float* __restrict__ esum)
{
    int e = blockIdx.x * blockDim.x + threadIdx.x;
    if (e >= ETOT) return;
    int s, d;
    if (e < E_EDGES) { s = src[e]; d = dst[e]; } else { s = d = e - E_EDGES; }
    float2 a  = *(const float2*)(als + s * 2);
    float2 b  = *(const float2*)(ald + d * 2);
    float2 mx = *(const float2*)(emax + d * 2);
    atomicAdd(&esum[d * 2 + 0], expf(lrelu(a.x + b.x) - mx.x));
    atomicAdd(&esum[d * 2 + 1], expf(lrelu(a.y + b.y) - mx.y));
}

// One warp per edge; lane owns 4 consecutive feature cols (coalesced 512B).
__global__ void edge_aggr_kernel(
    const int* __restrict__ src, const int* __restrict__ dst,
    const float* __restrict__ als, const float* __restrict__ ald,
    const float* __restrict__ emax, const float* __restrict__ esum,
    const float* __restrict__ h, float* __restrict__ agg)
{
    long long t = (long long)blockIdx.x * blockDim.x + threadIdx.x;
    int e = (int)(t >> 5);
    int lane = (int)(t & 31);
    if (e >= ETOT) return;
    int s, d;
    if (e < E_EDGES) { s = src[e]; d = dst[e]; } else { s = d = e - E_EDGES; }
    float2 a  = *(const float2*)(als + s * 2);
    float2 b  = *(const float2*)(ald + d * 2);
    float2 mx = *(const float2*)(emax + d * 2);
    float2 sm = *(const float2*)(esum + d * 2);
    float alpha0 = expf(lrelu(a.x + b.x) - mx.x) / sm.x;
    float alpha1 = expf(lrelu(a.y + b.y) - mx.y) / sm.y;
    float alpha  = (lane < 16) ? alpha0 : alpha1;

    float4 hv = *(const float4*)(h + (size_t)s * 128 + lane * 4);
    float* o = agg + (size_t)d * 128 + lane * 4;
    atomicAdd(o + 0, alpha * hv.x);
    atomicAdd(o + 1, alpha * hv.y);
    atomicAdd(o + 2, alpha * hv.z);
    atomicAdd(o + 3, alpha * hv.w);
}

__global__ void bias_act_kernel(float* __restrict__ buf,
                                const float* __restrict__ bias, int relu)
{
    int i = blockIdx.x * blockDim.x + threadIdx.x;
    if (i >= N_NODES * 128) return;
    float v = buf[i] + bias[i & 127];
    if (relu) v = fmaxf(v, 0.0f);
    buf[i] = v;
}

// ---------------- SAGE --------------------------------------------------------
__global__ void count_kernel(const int* __restrict__ dst, float* __restrict__ cnt)
{
    int e = blockIdx.x * blockDim.x + threadIdx.x;
    if (e >= E_EDGES) return;
    atomicAdd(&cnt[dst[e]], 1.0f);
}

// warp per edge; lane owns 2 cols of the 64-wide row.
__global__ void sage_aggr_kernel(
    const int* __restrict__ src, const int* __restrict__ dst,
    const float* __restrict__ y, float* __restrict__ msum)
{
    long long t = (long long)blockIdx.x * blockDim.x + threadIdx.x;
    int e = (int)(t >> 5);
    int lane = (int)(t & 31);
    if (e >= E_EDGES) return;
    int s = src[e], d = dst[e];
    float2 v = *(const float2*)(y + (size_t)s * 64 + lane * 2);
    float* o = msum + (size_t)d * 64 + lane * 2;
    atomicAdd(o + 0, v.x);
    atomicAdd(o + 1, v.y);
}

__global__ void sage_final_kernel(
    const float* __restrict__ msum, const float* __restrict__ cnt,
    const float* __restrict__ bl, const float* __restrict__ r,
    float* __restrict__ out)
{
    int i = blockIdx.x * blockDim.x + threadIdx.x;
    if (i >= N_NODES * 64) return;
    int n = i >> 6, c = i & 63;
    float m = msum[i] / fmaxf(cnt[n], 1.0f);
    out[i] = fmaxf(m + bl[c] + r[i], 0.0f);
}

__global__ void final_bn_kernel(
    const float* __restrict__ msum, const float* __restrict__ cnt,
    const float* __restrict__ bl, const float* __restrict__ r,
    const float* __restrict__ gamma, const float* __restrict__ beta,
    const float* __restrict__ mean, const float* __restrict__ var,
    float* __restrict__ out)
{
    int i = blockIdx.x * blockDim.x + threadIdx.x;
    if (i >= N_NODES * 64) return;
    int n = i >> 6, c = i & 63;
    float m = msum[i] / fmaxf(cnt[n], 1.0f);
    float v = fmaxf(m + bl[c] + r[i], 0.0f);
    out[i] = (v - mean[c]) * (gamma[c] * rsqrtf(var[c] + BN_EPS)) + beta[c];
}

// ---------------- host orchestration -----------------------------------------
static void run_gat_layer(const float* xin, int Kin, const float* W,
                          const float* asrc, const float* adst, const float* bias,
                          float* hbuf, float* aggbuf, int relu,
                          const int* src, const int* dst,
                          float* als, float* ald, float* emax, float* esum)
{
    dim3 gg((N_NODES + BM - 1) / BM, 128 / BN);
    sgemm_kernel<<<gg, 256>>>(xin, W, hbuf, N_NODES, Kin, 128);
    compute_al_kernel<<<(N_NODES + 7) / 8, 256>>>(hbuf, asrc, adst, als, ald);
    fill_kernel<<<(2 * N_NODES + 255) / 256, 256>>>(emax, -INFINITY, 2 * N_NODES);
    cudaMemsetAsync(esum, 0, (size_t)2 * N_NODES * sizeof(float), 0);
    cudaMemsetAsync(aggbuf, 0, (size_t)N_NODES * 128 * sizeof(float), 0);
    edge_max_kernel<<<(ETOT + 255) / 256, 256>>>(src, dst, als, ald, emax);
    edge_sum_kernel<<<(ETOT + 255) / 256, 256>>>(src, dst, als, ald, emax, esum);
    edge_aggr_kernel<<<(ETOT + 7) / 8, 256>>>(src, dst, als, ald, emax, esum,
                                              hbuf, aggbuf);
    bias_act_kernel<<<(N_NODES * 128 + 255) / 256, 256>>>(aggbuf, bias, relu);
}

extern "C" void kernel_launch(void* const* d_in, const int* in_sizes, int n_in,
                              void* d_out, int out_size)
{
    const float* x      = (const float*)d_in[0];
    const int*   ei     = (const int*)d_in[1];
    const float* W1     = (const float*)d_in[2];
    const float* a_src1 = (const float*)d_in[3];
    const float* a_dst1 = (const float*)d_in[4];
    const float* b1     = (const float*)d_in[5];
    const float* W2     = (const float*)d_in[6];
    const float* a_src2 = (const float*)d_in[7];
    const float* a_dst2 = (const float*)d_in[8];
    const float* b2     = (const float*)d_in[9];
    const float* s1wl   = (const float*)d_in[10];
    const float* s1bl   = (const float*)d_in[11];
    const float* s1wr   = (const float*)d_in[12];
    const float* s2wl   = (const float*)d_in[13];
    const float* s2bl   = (const float*)d_in[14];
    const float* s2wr   = (const float*)d_in[15];
    const float* bng    = (const float*)d_in[16];
    const float* bnb    = (const float*)d_in[17];
    const float* bnm    = (const float*)d_in[18];
    const float* bnv    = (const float*)d_in[19];
    float* out = (float*)d_out;

    const int* src = ei;
    const int* dst = ei + E_EDGES;

    float *A, *B, *C, *D, *Ebuf, *F, *als, *ald, *emax, *esum, *cnt;
    cudaGetSymbolAddress((void**)&A,    g_bufA);
    cudaGetSymbolAddress((void**)&B,    g_bufB);
    cudaGetSymbolAddress((void**)&C,    g_bufC);
    cudaGetSymbolAddress((void**)&D,    g_bufD);
    cudaGetSymbolAddress((void**)&Ebuf, g_bufE);
    cudaGetSymbolAddress((void**)&F,    g_bufF);
    cudaGetSymbolAddress((void**)&als,  g_als);
    cudaGetSymbolAddress((void**)&ald,  g_ald);
    cudaGetSymbolAddress((void**)&emax, g_emax);
    cudaGetSymbolAddress((void**)&esum, g_esum);
    cudaGetSymbolAddress((void**)&cnt,  g_cnt);

    // ---- GAT layer 1: h1=x@W1 in A, aggregate into B, B=relu(B+b1) ----
    run_gat_layer(x, 256, W1, a_src1, a_dst1, b1, A, B, 1, src, dst,
                  als, ald, emax, esum);

    // ---- GAT layer 2: h2=B@W2 in C, aggregate into A, A=A+b2 ----
    run_gat_layer(B, 128, W2, a_src2, a_dst2, b2, C, A, 0, src, dst,
                  als, ald, emax, esum);

    // ---- shared in-degree counts (original edges only) ----
    cudaMemsetAsync(cnt, 0, (size_t)N_NODES * sizeof(float), 0);
    count_kernel<<<(E_EDGES + 255) / 256, 256>>>(dst, cnt);

    dim3 g64((N_NODES + BM - 1) / BM, 64 / BN);

    // ---- SAGE layer 1 (linearity: project before aggregating) ----
    sgemm_kernel<<<g64, 256>>>(A, s1wl, D,    N_NODES, 128, 64);  // y1
    sgemm_kernel<<<g64, 256>>>(A, s1wr, Ebuf, N_NODES, 128, 64);  // r1
    cudaMemsetAsync(F, 0, (size_t)N_NODES * 64 * sizeof(float), 0);
    sage_aggr_kernel<<<(E_EDGES + 7) / 8, 256>>>(src, dst, D, F);
    sage_final_kernel<<<(N_NODES * 64 + 255) / 256, 256>>>(F, cnt, s1bl, Ebuf, D);

    // ---- SAGE layer 2 ----
    sgemm_kernel<<<g64, 256>>>(D, s2wl, Ebuf, N_NODES, 64, 64);   // y2
    sgemm_kernel<<<g64, 256>>>(D, s2wr, F,    N_NODES, 64, 64);   // r2
    cudaMemsetAsync(A, 0, (size_t)N_NODES * 64 * sizeof(float), 0);
    sage_aggr_kernel<<<(E_EDGES + 7) / 8, 256>>>(src, dst, Ebuf, A);
    final_bn_kernel<<<(N_NODES * 64 + 255) / 256, 256>>>(
        A, cnt, s2bl, F, bng, bnb, bnm, bnv, out);
}

// round 2
// speedup vs baseline: 2.9862x; 2.9862x over previous
#include <cuda_runtime.h>
#include <math.h>

#define N_NODES 50000
#define E_EDGES 1600000
#define NEG_SLOPE 0.2f
#define BN_EPS 1e-5f

// ---------------- scratch (static device globals; no allocation) ------------
__device__ float g_bufA[(size_t)N_NODES * 128];
__device__ float g_bufB[(size_t)N_NODES * 128];
__device__ float g_bufC[(size_t)N_NODES * 128];
__device__ float g_bufD[(size_t)N_NODES * 64];
__device__ float g_bufE[(size_t)N_NODES * 64];
__device__ float g_bufF[(size_t)N_NODES * 64];
__device__ float g_als[N_NODES * 2];
__device__ float g_ald[N_NODES * 2];
__device__ int   g_deg[N_NODES];
__device__ int   g_roff[N_NODES + 1];
__device__ int   g_cur[N_NODES];
__device__ int   g_esrc[E_EDGES];

// ---------------- helpers ----------------------------------------------------
__device__ __forceinline__ float lrelu(float x) {
    return x > 0.0f ? x : NEG_SLOPE * x;
}

// ---------------- CSR build ---------------------------------------------------
__global__ void hist_kernel(const int* __restrict__ dst, int* __restrict__ deg)
{
    int e = blockIdx.x * blockDim.x + threadIdx.x;
    if (e < E_EDGES) atomicAdd(&deg[dst[e]], 1);
}

// single block, 1024 threads: exclusive scan of deg into roff (and cur copy)
__global__ __launch_bounds__(1024) void scan_kernel(
    const int* __restrict__ deg, int* __restrict__ roff, int* __restrict__ cur)
{
    __shared__ int part[1024];
    const int CH = (N_NODES + 1023) / 1024;
    int t = threadIdx.x;
    int base = t * CH;
    int sum = 0;
    for (int i = 0; i < CH; i++) {
        int idx = base + i;
        if (idx < N_NODES) sum += deg[idx];
    }
    part[t] = sum;
    __syncthreads();
    // Hillis-Steele inclusive scan
    for (int off = 1; off < 1024; off <<= 1) {
        int v = (t >= off) ? part[t - off] : 0;
        __syncthreads();
        part[t] += v;
        __syncthreads();
    }
    int run = part[t] - sum;   // exclusive prefix of this thread's chunk
    for (int i = 0; i < CH; i++) {
        int idx = base + i;
        if (idx < N_NODES) {
            roff[idx] = run;
            cur[idx]  = run;
            run += deg[idx];
        }
    }
    if (t == 1023) roff[N_NODES] = run;
}

__global__ void scatter_kernel(const int* __restrict__ src,
                               const int* __restrict__ dst,
                               int* __restrict__ cur, int* __restrict__ esrc)
{
    int e = blockIdx.x * blockDim.x + threadIdx.x;
    if (e >= E_EDGES) return;
    int d = dst[e];
    int p = atomicAdd(&cur[d], 1);
    esrc[p] = src[e];
}

// ---------------- SGEMM: C[M,NC] = A[M,K] @ B[K,NC] -------------------------
#define BM 128
#define BN 64
#define BK 16
#define TM 8
#define TN 4

__global__ __launch_bounds__(256) void sgemm_kernel(
    const float* __restrict__ A, const float* __restrict__ B,
    float* __restrict__ C, int M, int K, int NC)
{
    __shared__ float As[BK][BM];
    __shared__ float Bs[BK][BN];

    int tid = threadIdx.x;
    int rowBase = blockIdx.x * BM;
    int colBase = blockIdx.y * BN;
    int tx = tid & 15;
    int ty = tid >> 4;

    float acc[TM][TN];
    #pragma unroll
    for (int i = 0; i < TM; i++)
        #pragma unroll
        for (int j = 0; j < TN; j++) acc[i][j] = 0.0f;

    int ar0 = tid >> 2;
    int ac  = (tid & 3) * 4;
    int br  = tid >> 4;
    int bc  = (tid & 15) * 4;

    for (int k0 = 0; k0 < K; k0 += BK) {
        #pragma unroll
        for (int i = 0; i < 2; i++) {
            int r  = ar0 + i * 64;
            int gr = rowBase + r;
            float4 v = make_float4(0.f, 0.f, 0.f, 0.f);
            if (gr < M) v = *(const float4*)(A + (size_t)gr * K + k0 + ac);
            As[ac + 0][r] = v.x;
            As[ac + 1][r] = v.y;
            As[ac + 2][r] = v.z;
            As[ac + 3][r] = v.w;
        }
        {
            float4 v = *(const float4*)(B + (size_t)(k0 + br) * NC + colBase + bc);
            Bs[br][bc + 0] = v.x;
            Bs[br][bc + 1] = v.y;
            Bs[br][bc + 2] = v.z;
            Bs[br][bc + 3] = v.w;
        }
        __syncthreads();

        #pragma unroll
        for (int kk = 0; kk < BK; kk++) {
            float a[TM], b[TN];
            #pragma unroll
            for (int i = 0; i < TM; i++) a[i] = As[kk][ty * TM + i];
            #pragma unroll
            for (int j = 0; j < TN; j++) b[j] = Bs[kk][tx * TN + j];
            #pragma unroll
            for (int i = 0; i < TM; i++)
                #pragma unroll
                for (int j = 0; j < TN; j++) acc[i][j] = fmaf(a[i], b[j], acc[i][j]);
        }
        __syncthreads();
    }

    #pragma unroll
    for (int i = 0; i < TM; i++) {
        int gr = rowBase + ty * TM + i;
        if (gr < M) {
            float4 v = make_float4(acc[i][0], acc[i][1], acc[i][2], acc[i][3]);
            *(float4*)(C + (size_t)gr * NC + colBase + tx * TN) = v;
        }
    }
}

// ---------------- GAT attention-logit precompute -----------------------------
__global__ void compute_al_kernel(
    const float* __restrict__ h, const float* __restrict__ a_src,
    const float* __restrict__ a_dst, float* __restrict__ als,
    float* __restrict__ ald)
{
    int warp = (blockIdx.x * blockDim.x + threadIdx.x) >> 5;
    int lane = threadIdx.x & 31;
    if (warp >= N_NODES) return;

    float4 hv = *(const float4*)(h + (size_t)warp * 128 + lane * 4);
    float4 as = *(const float4*)(a_src + lane * 4);
    float4 ad = *(const float4*)(a_dst + lane * 4);
    float ss = hv.x * as.x + hv.y * as.y + hv.z * as.z + hv.w * as.w;
    float sd = hv.x * ad.x + hv.y * ad.y + hv.z * ad.z + hv.w * ad.w;
    #pragma unroll
    for (int o = 8; o; o >>= 1) {
        ss += __shfl_xor_sync(0xffffffffu, ss, o);
        sd += __shfl_xor_sync(0xffffffffu, sd, o);
    }
    if (lane == 0)  { als[warp * 2 + 0] = ss; ald[warp * 2 + 0] = sd; }
    if (lane == 16) { als[warp * 2 + 1] = ss; ald[warp * 2 + 1] = sd; }
}

// ---------------- fused GAT gather (softmax + aggregate + bias + act) --------
// one warp per destination node; lane owns 4 feature columns.
__global__ __launch_bounds__(256) void gat_gather_kernel(
    const int* __restrict__ roff, const int* __restrict__ esrc,
    const float* __restrict__ als, const float* __restrict__ ald,
    const float* __restrict__ h, const float* __restrict__ bias,
    float* __restrict__ out, int relu)
{
    int d = (blockIdx.x * blockDim.x + threadIdx.x) >> 5;
    int lane = threadIdx.x & 31;
    if (d >= N_NODES) return;

    float2 ad = *(const float2*)(ald + 2 * d);
    float2 a_self = *(const float2*)(als + 2 * d);
    float es0 = lrelu(a_self.x + ad.x);
    float es1 = lrelu(a_self.y + ad.y);

    int beg = roff[d], end = roff[d + 1];

    // --- pass 1: max over incoming edges (incl. self) ---
    float m0 = es0, m1 = es1;
    for (int i = beg + lane; i < end; i += 32) {
        int s = __ldg(esrc + i);
        float2 a = *(const float2*)(als + 2 * s);
        m0 = fmaxf(m0, lrelu(a.x + ad.x));
        m1 = fmaxf(m1, lrelu(a.y + ad.y));
    }
    #pragma unroll
    for (int o = 16; o; o >>= 1) {
        m0 = fmaxf(m0, __shfl_xor_sync(0xffffffffu, m0, o));
        m1 = fmaxf(m1, __shfl_xor_sync(0xffffffffu, m1, o));
    }

    // --- pass 2: exp-sum ---
    float s0 = 0.0f, s1 = 0.0f;
    for (int i = beg + lane; i < end; i += 32) {
        int s = __ldg(esrc + i);
        float2 a = *(const float2*)(als + 2 * s);
        s0 += expf(lrelu(a.x + ad.x) - m0);
        s1 += expf(lrelu(a.y + ad.y) - m1);
    }
    #pragma unroll
    for (int o = 16; o; o >>= 1) {
        s0 += __shfl_xor_sync(0xffffffffu, s0, o);
        s1 += __shfl_xor_sync(0xffffffffu, s1, o);
    }
    s0 += expf(es0 - m0);
    s1 += expf(es1 - m1);
    float inv0 = 1.0f / s0, inv1 = 1.0f / s1;

    // --- pass 3: weighted feature accumulation ---
    // lanes 0..15 -> head 0 (cols 0..63), lanes 16..31 -> head 1
    float mh   = (lane < 16) ? m0 : m1;
    float invh = (lane < 16) ? inv0 : inv1;
    float adh  = (lane < 16) ? ad.x : ad.y;
    float esh  = (lane < 16) ? es0 : es1;

    float alpha_self = expf(esh - mh) * invh;
    float4 hv = *(const float4*)(h + (size_t)d * 128 + lane * 4);
    float4 acc;
    acc.x = alpha_self * hv.x;
    acc.y = alpha_self * hv.y;
    acc.z = alpha_self * hv.z;
    acc.w = alpha_self * hv.w;

    for (int i = beg; i < end; i++) {
        int s = __ldg(esrc + i);                 // broadcast load
        float a = __ldg(als + 2 * s + (lane < 16 ? 0 : 1));
        float alpha = expf(lrelu(a + adh) - mh) * invh;
        float4 v = *(const float4*)(h + (size_t)s * 128 + lane * 4);
        acc.x = fmaf(alpha, v.x, acc.x);
        acc.y = fmaf(alpha, v.y, acc.y);
        acc.z = fmaf(alpha, v.z, acc.z);
        acc.w = fmaf(alpha, v.w, acc.w);
    }

    float4 b = *(const float4*)(bias + lane * 4);
    acc.x += b.x; acc.y += b.y; acc.z += b.z; acc.w += b.w;
    if (relu) {
        acc.x = fmaxf(acc.x, 0.0f);
        acc.y = fmaxf(acc.y, 0.0f);
        acc.z = fmaxf(acc.z, 0.0f);
        acc.w = fmaxf(acc.w, 0.0f);
    }
    *(float4*)(out + (size_t)d * 128 + lane * 4) = acc;
}

// ---------------- fused SAGE gather (mean + bias + root + relu [+ BN]) -------
// one warp per destination node; lane owns 2 feature columns (64 wide).
__global__ __launch_bounds__(256) void sage_gather_kernel(
    const int* __restrict__ roff, const int* __restrict__ esrc,
    const float* __restrict__ y, const float* __restrict__ bl,
    const float* __restrict__ r, float* __restrict__ out,
    const float* __restrict__ gamma, const float* __restrict__ beta,
    const float* __restrict__ mean, const float* __restrict__ var,
    int do_bn)
{
    int d = (blockIdx.x * blockDim.x + threadIdx.x) >> 5;
    int lane = threadIdx.x & 31;
    if (d >= N_NODES) return;

    int beg = roff[d], end = roff[d + 1];
    float ax = 0.0f, ay = 0.0f;
    for (int i = beg; i < end; i++) {
        int s = __ldg(esrc + i);
        float2 v = *(const float2*)(y + (size_t)s * 64 + lane * 2);
        ax += v.x;
        ay += v.y;
    }
    float invc = 1.0f / fmaxf((float)(end - beg), 1.0f);
    int c = lane * 2;
    float2 bb = *(const float2*)(bl + c);
    float2 rr = *(const float2*)(r + (size_t)d * 64 + c);
    float vx = fmaxf(ax * invc + bb.x + rr.x, 0.0f);
    float vy = fmaxf(ay * invc + bb.y + rr.y, 0.0f);
    if (do_bn) {
        float sx = gamma[c]     * rsqrtf(var[c]     + BN_EPS);
        float sy = gamma[c + 1] * rsqrtf(var[c + 1] + BN_EPS);
        vx = (vx - mean[c])     * sx + beta[c];
        vy = (vy - mean[c + 1]) * sy + beta[c + 1];
    }
    float2 o = make_float2(vx, vy);
    *(float2*)(out + (size_t)d * 64 + c) = o;
}

// ---------------- host orchestration -----------------------------------------
extern "C" void kernel_launch(void* const* d_in, const int* in_sizes, int n_in,
                              void* d_out, int out_size)
{
    const float* x      = (const float*)d_in[0];
    const int*   ei     = (const int*)d_in[1];
    const float* W1     = (const float*)d_in[2];
    const float* a_src1 = (const float*)d_in[3];
    const float* a_dst1 = (const float*)d_in[4];
    const float* b1     = (const float*)d_in[5];
    const float* W2     = (const float*)d_in[6];
    const float* a_src2 = (const float*)d_in[7];
    const float* a_dst2 = (const float*)d_in[8];
    const float* b2     = (const float*)d_in[9];
    const float* s1wl   = (const float*)d_in[10];
    const float* s1bl   = (const float*)d_in[11];
    const float* s1wr   = (const float*)d_in[12];
    const float* s2wl   = (const float*)d_in[13];
    const float* s2bl   = (const float*)d_in[14];
    const float* s2wr   = (const float*)d_in[15];
    const float* bng    = (const float*)d_in[16];
    const float* bnb    = (const float*)d_in[17];
    const float* bnm    = (const float*)d_in[18];
    const float* bnv    = (const float*)d_in[19];
    float* out = (float*)d_out;

    const int* src = ei;
    const int* dst = ei + E_EDGES;

    float *A, *B, *C, *D, *Ebuf, *F, *als, *ald;
    int *deg, *roff, *cur, *esrc;
    cudaGetSymbolAddress((void**)&A,    g_bufA);
    cudaGetSymbolAddress((void**)&B,    g_bufB);
    cudaGetSymbolAddress((void**)&C,    g_bufC);
    cudaGetSymbolAddress((void**)&D,    g_bufD);
    cudaGetSymbolAddress((void**)&Ebuf, g_bufE);
    cudaGetSymbolAddress((void**)&F,    g_bufF);
    cudaGetSymbolAddress((void**)&als,  g_als);
    cudaGetSymbolAddress((void**)&ald,  g_ald);
    cudaGetSymbolAddress((void**)&deg,  g_deg);
    cudaGetSymbolAddress((void**)&roff, g_roff);
    cudaGetSymbolAddress((void**)&cur,  g_cur);
    cudaGetSymbolAddress((void**)&esrc, g_esrc);

    // ---- CSR build (by dst) ----
    cudaMemsetAsync(deg, 0, N_NODES * sizeof(int), 0);
    hist_kernel<<<(E_EDGES + 255) / 256, 256>>>(dst, deg);
    scan_kernel<<<1, 1024>>>(deg, roff, cur);
    scatter_kernel<<<(E_EDGES + 255) / 256, 256>>>(src, dst, cur, esrc);

    dim3 gg((N_NODES + BM - 1) / BM, 128 / BN);
    dim3 g64((N_NODES + BM - 1) / BM, 64 / BN);
    int gatherBlocks = (N_NODES * 32 + 255) / 256;

    // ---- GAT layer 1: h1 = x@W1 -> A, gather -> B (relu) ----
    sgemm_kernel<<<gg, 256>>>(x, W1, A, N_NODES, 256, 128);
    compute_al_kernel<<<(N_NODES + 7) / 8, 256>>>(A, a_src1, a_dst1, als, ald);
    gat_gather_kernel<<<gatherBlocks, 256>>>(roff, esrc, als, ald, A, b1, B, 1);

    // ---- GAT layer 2: h2 = B@W2 -> C, gather -> A (no relu) ----
    sgemm_kernel<<<gg, 256>>>(B, W2, C, N_NODES, 128, 128);
    compute_al_kernel<<<(N_NODES + 7) / 8, 256>>>(C, a_src2, a_dst2, als, ald);
    gat_gather_kernel<<<gatherBlocks, 256>>>(roff, esrc, als, ald, C, b2, A, 0);

    // ---- SAGE layer 1: project first (linearity), gather-mean, fuse epi ----
    sgemm_kernel<<<g64, 256>>>(A, s1wl, D,    N_NODES, 128, 64);  // y1
    sgemm_kernel<<<g64, 256>>>(A, s1wr, Ebuf, N_NODES, 128, 64);  // r1
    sage_gather_kernel<<<gatherBlocks, 256>>>(roff, esrc, D, s1bl, Ebuf, F,
                                              nullptr, nullptr, nullptr, nullptr, 0);

    // ---- SAGE layer 2 + BN fused ----
    sgemm_kernel<<<g64, 256>>>(F, s2wl, D,    N_NODES, 64, 64);   // y2
    sgemm_kernel<<<g64, 256>>>(F, s2wr, Ebuf, N_NODES, 64, 64);   // r2
    sage_gather_kernel<<<gatherBlocks, 256>>>(roff, esrc, D, s2bl, Ebuf, out,
                                              bng, bnb, bnm, bnv, 1);
}